// round 14
// baseline (speedup 1.0000x reference)
#include <cuda_runtime.h>
#include <cuda_fp16.h>

// ---------------------------------------------------------------------------
// SlatewiseGRU, warp-specialized: per CTA (256 thr, 32 seqs),
//   warps 0-3 (P): x-side GEMM -> gx ring (fp16, 2 stages) via mma.sync fp16
//   warps 4-7 (C): h-side GEMM + epilogue (MUFU.TANH) + h update + output
// P/C handoff: named-barrier full/empty pairs per ring stage.
// C runs each step in two m16-halves (acc=48 regs). h state fp16 hi+lo;
// matvec inputs single fp16 plane (R12 numerics) + gx fp16 (new source).
// ---------------------------------------------------------------------------

#define DD   128
#define LL   32
#define NSEQ 8192
#define TN   32
#define NTHR 256
#define NCTA (NSEQ / TN)   // 256
#define SMP  136           // x/h SMEM row stride (fp16); row = 272 B
#define GXP  400           // gx row stride (fp16): 384 + 16 pad

// Packed B-fragments: [wt:2 (ih,hh)][kt:8][ntile:48 (gg*16 + blk)][lane:32]
__device__ uint2 g_wpack[2 * 8 * 48 * 32];

__global__ void prep_weights(const float* __restrict__ W_ih,
                             const float* __restrict__ W_hh) {
    int idx = blockIdx.x * blockDim.x + threadIdx.x;
    if (idx >= 2 * 8 * 48 * 32) return;
    int l  = idx & 31;
    int r  = idx >> 5;
    int nt = r % 48; r /= 48;
    int kt = r % 8;  r /= 8;
    int wt = r;
    const float* W = wt ? W_hh : W_ih;
    int gg = nt / 16, b = nt % 16;
    int j  = gg * 128 + b * 8 + (l >> 2);
    int d0 = kt * 16 + (l & 3) * 2;
    unsigned short e[4];
    #pragma unroll
    for (int q = 0; q < 4; ++q) {
        int d = d0 + (q & 1) + (q >> 1) * 8;
        e[q] = __half_as_ushort(__float2half_rn(W[j * DD + d]));
    }
    uint2 v;
    v.x = (unsigned)e[0] | ((unsigned)e[1] << 16);
    v.y = (unsigned)e[2] | ((unsigned)e[3] << 16);
    g_wpack[idx] = v;
}

__device__ __forceinline__ unsigned pkh(__half a, __half b) {
    return (unsigned)__half_as_ushort(a) | ((unsigned)__half_as_ushort(b) << 16);
}
__device__ __forceinline__ float hlo(unsigned u) {
    return __half2float(__ushort_as_half((unsigned short)(u & 0xffffu)));
}
__device__ __forceinline__ float hhi(unsigned u) {
    return __half2float(__ushort_as_half((unsigned short)(u >> 16)));
}

__device__ __forceinline__ void mma16816(float* c, const unsigned* a, uint2 b) {
    asm volatile(
        "mma.sync.aligned.m16n8k16.row.col.f32.f16.f16.f32 "
        "{%0,%1,%2,%3}, {%4,%5,%6,%7}, {%8,%9}, {%0,%1,%2,%3};\n"
        : "+f"(c[0]), "+f"(c[1]), "+f"(c[2]), "+f"(c[3])
        : "r"(a[0]), "r"(a[1]), "r"(a[2]), "r"(a[3]), "r"(b.x), "r"(b.y));
}

__device__ __forceinline__ void ldsm4(unsigned* r, unsigned addr) {
    asm volatile("ldmatrix.sync.aligned.m8n8.x4.shared.b16 {%0,%1,%2,%3}, [%4];"
                 : "=r"(r[0]), "=r"(r[1]), "=r"(r[2]), "=r"(r[3]) : "r"(addr));
}

__device__ __forceinline__ float tanh_mufu(float x) {
    float y;
    asm("tanh.approx.f32 %0, %1;" : "=f"(y) : "f"(x));
    return y;
}
__device__ __forceinline__ float sigm(float x) {
    return fmaf(tanh_mufu(0.5f * x), 0.5f, 0.5f);
}

#define BARSYNC(id, n)   asm volatile("bar.sync %0, %1;"   :: "r"(id), "r"(n) : "memory")
#define BARARRIVE(id, n) asm volatile("bar.arrive %0, %1;" :: "r"(id), "r"(n) : "memory")

extern __shared__ char smraw[];

__global__ void __launch_bounds__(NTHR, 2)
gru_ws(const float* __restrict__ item,   // [N, L, D]
       const float* __restrict__ user,   // [N, D]
       const float* __restrict__ b_ih,   // [384]
       const float* __restrict__ b_hh,   // [384]
       const float* __restrict__ W_out,  // [128]
       const float* __restrict__ b_out,  // [1]
       float* __restrict__ out)          // [N, L]
{
    // SMEM: xring[2][TN*SMP] | hh | hl | gx[2][32*GXP] | outb[2][4][32] | Bs
    unsigned short* xring = (unsigned short*)smraw;
    unsigned short* hh = xring + 2 * TN * SMP;
    unsigned short* hl = hh + TN * SMP;
    unsigned short* gx = hl + TN * SMP;
    float* outb = (float*)(gx + 2 * 32 * GXP);   // [2][4][32]
    float* Bs   = outb + 256;                    // [512]

    const int tid = threadIdx.x;
    const int w   = tid >> 5;
    const int l   = tid & 31;
    const int g   = l >> 2;
    const int tg  = l & 3;
    const int w4  = w & 3;
    const int nBase = blockIdx.x * TN;

    // Biases: [0:256) b_ih+b_hh for r,z; [256:384) b_ih n; [384:512) b_hh n.
    for (int i = tid; i < 512; i += NTHR) {
        float v;
        if (i < 256)      v = b_ih[i] + b_hh[i];
        else if (i < 384) v = b_ih[i];
        else              v = b_hh[i - 128];
        Bs[i] = v;
    }

    const int rowsel = l & 15;
    const int halfc  = l >> 4;
    const unsigned lmOff = (unsigned)((rowsel * SMP + halfc * 8) * 2);
    const unsigned xrA = (unsigned)__cvta_generic_to_shared(xring) + lmOff;
    const unsigned hhA = (unsigned)__cvta_generic_to_shared(hh) + lmOff;

    // ---- prologue (divergent work, converged barrier) ----
    if (w < 4) {
        // P: stage x_0 -> ring0, x_1 -> ring1 (fp16 single plane)
        for (int tt = 0; tt < 2; ++tt)
            #pragma unroll
            for (int i = 0; i < 8; ++i) {
                int idx = tid + i * 128;
                int row = idx >> 5, c4 = (idx & 31) * 4;
                float4 v = *(const float4*)(item +
                             ((size_t)(nBase + row) * LL + tt) * DD + c4);
                uint2 hv;
                hv.x = pkh(__float2half_rn(v.x), __float2half_rn(v.y));
                hv.y = pkh(__float2half_rn(v.z), __float2half_rn(v.w));
                *(uint2*)&xring[tt * TN * SMP + row * SMP + c4] = hv;
            }
    } else {
        // C: h0 = user_embs (fp16 hi/lo), owner-thread init
        #pragma unroll
        for (int half = 0; half < 2; ++half)
            #pragma unroll
            for (int rh = 0; rh < 2; ++rh) {
                int row = g + rh * 8 + half * 16;
                #pragma unroll
                for (int j = 0; j < 4; ++j) {
                    int uu = w4 * 32 + j * 8 + tg * 2;
                    float2 v = *(const float2*)(user +
                                 (size_t)(nBase + row) * DD + uu);
                    __half a0 = __float2half_rn(v.x);
                    __half a1 = __float2half_rn(v.y);
                    *(unsigned*)&hh[row * SMP + uu] = pkh(a0, a1);
                    *(unsigned*)&hl[row * SMP + uu] =
                        pkh(__float2half_rn(v.x - __half2float(a0)),
                            __float2half_rn(v.y - __half2float(a1)));
                }
            }
    }
    __syncthreads();   // x0, x1, h0, biases visible to everyone

    if (w < 4) {
        // ================= PRODUCER: x-side GEMM -> gx ring =================
        for (int t = 0; t < LL; ++t) {
            const int s = t & 1;
            const unsigned xA = xrA + s * (TN * SMP * 2);
            unsigned short* gxs = gx + s * 32 * GXP;

            #pragma unroll
            for (int half = 0; half < 2; ++half) {
                float acc[3][4][4];
                #pragma unroll
                for (int a0 = 0; a0 < 3; ++a0)
                    #pragma unroll
                    for (int a1 = 0; a1 < 4; ++a1)
                        #pragma unroll
                        for (int a2 = 0; a2 < 4; ++a2) acc[a0][a1][a2] = 0.f;

                #pragma unroll
                for (int kt = 0; kt < 8; ++kt) {
                    uint2 Bw[3][4];
                    #pragma unroll
                    for (int gg = 0; gg < 3; ++gg)
                        #pragma unroll
                        for (int j = 0; j < 4; ++j)
                            Bw[gg][j] = g_wpack[kt * 1536 +
                                        (gg * 16 + w4 * 4 + j) * 32 + l];
                    unsigned a[4];
                    ldsm4(a, xA + half * (16 * SMP * 2) + kt * 32);
                    #pragma unroll
                    for (int gg = 0; gg < 3; ++gg)
                        #pragma unroll
                        for (int j = 0; j < 4; ++j)
                            mma16816(acc[gg][j], a, Bw[gg][j]);
                }

                if (half == 0 && t >= 2) BARSYNC(6 + s, 256);  // wait empty[s]

                // store gx (fp16) for this half
                #pragma unroll
                for (int gg = 0; gg < 3; ++gg)
                    #pragma unroll
                    for (int j = 0; j < 4; ++j)
                        #pragma unroll
                        for (int rh = 0; rh < 2; ++rh) {
                            int row = g + rh * 8 + half * 16;
                            int uu  = w4 * 32 + j * 8 + tg * 2;
                            unsigned pv = pkh(__float2half_rn(acc[gg][j][rh * 2]),
                                              __float2half_rn(acc[gg][j][rh * 2 + 1]));
                            *(unsigned*)&gxs[row * GXP + gg * 128 + uu] = pv;
                        }
            }
            BARARRIVE(4 + s, 256);   // full[s]

            if (t + 2 < LL) {
                BARSYNC(2, 128);     // all P reads of xring[s] complete
                #pragma unroll
                for (int i = 0; i < 8; ++i) {
                    int idx = tid + i * 128;
                    int row = idx >> 5, c4 = (idx & 31) * 4;
                    float4 v = *(const float4*)(item +
                                 ((size_t)(nBase + row) * LL + (t + 2)) * DD + c4);
                    uint2 hv;
                    hv.x = pkh(__float2half_rn(v.x), __float2half_rn(v.y));
                    hv.y = pkh(__float2half_rn(v.z), __float2half_rn(v.w));
                    *(uint2*)&xring[s * TN * SMP + row * SMP + c4] = hv;
                }
            }
        }
    } else {
        // ================= CONSUMER: h-side GEMM + epilogue =================
        float2 wo[4];
        #pragma unroll
        for (int j = 0; j < 4; ++j)
            wo[j] = *(const float2*)(W_out + w4 * 32 + j * 8 + tg * 2);
        const float bo = b_out[0];

        for (int t = 0; t < LL; ++t) {
            const int s = t & 1;
            unsigned short* gxs = gx + s * 32 * GXP;

            BARSYNC(3, 128);   // orders epi(t-1) h/outb writes before reads

            if (w == 4 && t > 0) {   // out reduction for step t-1
                float sum = bo;
                #pragma unroll
                for (int ww = 0; ww < 4; ++ww)
                    sum += outb[((t - 1) & 1) * 128 + ww * 32 + l];
                out[(size_t)(nBase + l) * LL + (t - 1)] = sum;
            }

            #pragma unroll
            for (int half = 0; half < 2; ++half) {
                float acc[3][4][4];
                #pragma unroll
                for (int a0 = 0; a0 < 3; ++a0)
                    #pragma unroll
                    for (int a1 = 0; a1 < 4; ++a1)
                        #pragma unroll
                        for (int a2 = 0; a2 < 4; ++a2) acc[a0][a1][a2] = 0.f;

                #pragma unroll
                for (int kt = 0; kt < 8; ++kt) {
                    uint2 Bw[3][4];
                    #pragma unroll
                    for (int gg = 0; gg < 3; ++gg)
                        #pragma unroll
                        for (int j = 0; j < 4; ++j)
                            Bw[gg][j] = g_wpack[(8 + kt) * 1536 +
                                        (gg * 16 + w4 * 4 + j) * 32 + l];
                    unsigned a[4];
                    ldsm4(a, hhA + half * (16 * SMP * 2) + kt * 32);
                    #pragma unroll
                    for (int gg = 0; gg < 3; ++gg)
                        #pragma unroll
                        for (int j = 0; j < 4; ++j)
                            mma16816(acc[gg][j], a, Bw[gg][j]);
                }

                BARSYNC(3, 128);                  // all C ldsm of this half done
                if (half == 0) BARSYNC(4 + s, 256);   // full[s]: gx ready

                // epilogue for this half's rows
                #pragma unroll
                for (int rh = 0; rh < 2; ++rh) {
                    int row = g + rh * 8 + half * 16;
                    float p = 0.f;
                    #pragma unroll
                    for (int j = 0; j < 4; ++j) {
                        int uu = w4 * 32 + j * 8 + tg * 2;
                        unsigned gr = *(const unsigned*)&gxs[row * GXP + uu];
                        unsigned gz = *(const unsigned*)&gxs[row * GXP + 128 + uu];
                        unsigned gn = *(const unsigned*)&gxs[row * GXP + 256 + uu];
                        float r0 = sigm(acc[0][j][rh * 2]     + hlo(gr) + Bs[uu]);
                        float r1 = sigm(acc[0][j][rh * 2 + 1] + hhi(gr) + Bs[uu + 1]);
                        float z0 = sigm(acc[1][j][rh * 2]     + hlo(gz) + Bs[128 + uu]);
                        float z1 = sigm(acc[1][j][rh * 2 + 1] + hhi(gz) + Bs[128 + uu + 1]);
                        float n0 = tanh_mufu(hlo(gn) + Bs[256 + uu]
                                   + r0 * (acc[2][j][rh * 2]     + Bs[384 + uu]));
                        float n1 = tanh_mufu(hhi(gn) + Bs[256 + uu + 1]
                                   + r1 * (acc[2][j][rh * 2 + 1] + Bs[384 + uu + 1]));
                        unsigned ohv = *(const unsigned*)&hh[row * SMP + uu];
                        unsigned olv = *(const unsigned*)&hl[row * SMP + uu];
                        float ho0 = hlo(ohv) + hlo(olv);
                        float ho1 = hhi(ohv) + hhi(olv);
                        float hn0 = (1.f - z0) * n0 + z0 * ho0;
                        float hn1 = (1.f - z1) * n1 + z1 * ho1;
                        __half p0 = __float2half_rn(hn0);
                        __half p1 = __float2half_rn(hn1);
                        *(unsigned*)&hh[row * SMP + uu] = pkh(p0, p1);
                        *(unsigned*)&hl[row * SMP + uu] =
                            pkh(__float2half_rn(hn0 - __half2float(p0)),
                                __float2half_rn(hn1 - __half2float(p1)));
                        p += hn0 * wo[j].x + hn1 * wo[j].y;
                    }
                    p += __shfl_xor_sync(0xffffffffu, p, 1);
                    p += __shfl_xor_sync(0xffffffffu, p, 2);
                    if (tg == 0) outb[(t & 1) * 128 + w4 * 32 + row] = p;
                }
            }
            BARARRIVE(6 + s, 256);   // empty[s]: gx[s] fully consumed
        }

        BARSYNC(3, 128);
        if (w == 4) {
            float sum = bo;
            #pragma unroll
            for (int ww = 0; ww < 4; ++ww)
                sum += outb[((LL - 1) & 1) * 128 + ww * 32 + l];
            out[(size_t)(nBase + l) * LL + (LL - 1)] = sum;
        }
    }
}

extern "C" void kernel_launch(void* const* d_in, const int* in_sizes, int n_in,
                              void* d_out, int out_size) {
    const float* item  = (const float*)d_in[0];
    const float* user  = (const float*)d_in[1];
    const float* W_ih  = (const float*)d_in[2];
    const float* W_hh  = (const float*)d_in[3];
    const float* b_ih  = (const float*)d_in[4];
    const float* b_hh  = (const float*)d_in[5];
    const float* W_out = (const float*)d_in[6];
    const float* b_out = (const float*)d_in[7];
    float* out = (float*)d_out;

    prep_weights<<<(2 * 8 * 48 * 32 + 255) / 256, 256>>>(W_ih, W_hh);

    size_t smem = (size_t)(2 * TN * SMP + 2 * TN * SMP / 2 * 0) * 0; // (unused)
    smem = (size_t)(2 * TN * SMP) * 2      // xring
         + (size_t)(2 * TN * SMP) * 2      // hh + hl
         + (size_t)(2 * 32 * GXP) * 2      // gx ring
         + 256 * sizeof(float)             // outb[2][4][32]
         + 512 * sizeof(float);            // biases
    // = 17408 + 17408 + 51200 + 1024 + 2048 = 89088 B/CTA -> 2 CTAs/SM OK
    cudaFuncSetAttribute(gru_ws,
                         cudaFuncAttributeMaxDynamicSharedMemorySize, (int)smem);
    gru_ws<<<NCTA, NTHR, smem>>>(item, user, b_ih, b_hh, W_out, b_out, out);
}